// round 12
// baseline (speedup 1.0000x reference)
#include <cuda_runtime.h>
#include <cstdint>

// Problem constants: B=8, S=2048, D=256
static constexpr int Bn = 8;
static constexpr int Sn = 2048;
static constexpr int Dn = 256;
static constexpr int MROWS = Bn * Sn;   // 16384

// k-dim permutation within each 8-col group: q -> ((q&3)<<1)|(q>>2)
__host__ __device__ __forceinline__ int pidx(int c) {
    return (c & ~7) | (((c & 3) << 1) | ((c >> 2) & 1));
}

// ---------------- device scratch (no cudaMalloc allowed) ----------------
__device__ __align__(16) float g_P[MROWS * Dn];      // head @ U, tf32-rounded, k-permuted
__device__ __align__(16) float g_UT[Dn * Dn];        // U^T,  tf32-rounded, k-permuted
__device__ float g_hs[MROWS];
__device__ float g_ds[MROWS];

__device__ __forceinline__ float rnd_tf32(float x) {
    uint32_t r; asm("cvt.rna.tf32.f32 %0, %1;" : "=r"(r) : "f"(x));
    return __uint_as_float(r);
}
__device__ __forceinline__ uint32_t f2tf(float x) {
    uint32_t r; asm("cvt.rna.tf32.f32 %0, %1;" : "=r"(r) : "f"(x));
    return r;
}

// ---------------- prep: hs/ds row dots (stream read) + UT tile-transpose ----------------
static constexpr int ROW_BLOCKS = (2 * MROWS) / 32;   // 1024 (4 rows/warp, 8 warps)
static constexpr int UT_BLOCKS = 16;                  // 64x64 tiles of U

__global__ void __launch_bounds__(256) prep_all(const float* __restrict__ head,
                                                const float* __restrict__ dep,
                                                const float* __restrict__ U,
                                                const float* __restrict__ W) {
    __shared__ float tile[64][65];
    int bid = blockIdx.x;
    int tid = threadIdx.x, w = tid >> 5, lane = tid & 31;

    if (bid < ROW_BLOCKS) {
        int idx0 = bid * 32;                    // block handles 32 rows
        bool isHead = idx0 < MROWS;             // blocks never straddle (MROWS%32==0)
        const float* src = isHead ? head : dep;
        float* dst       = isHead ? g_hs : g_ds;
        const float* wvp = isHead ? W : (W + Dn);
        int base = (isHead ? idx0 : idx0 - MROWS) + w * 4;
        float4 w0 = *(const float4*)(wvp + lane * 8);
        float4 w1 = *(const float4*)(wvp + lane * 8 + 4);
        float p[4];
        #pragma unroll
        for (int rit = 0; rit < 4; rit++) {
            const float* sp = src + (size_t)(base + rit) * Dn + lane * 8;
            float4 a0 = *(const float4*)sp;
            float4 a1 = *(const float4*)(sp + 4);
            p[rit] = a0.x * w0.x + a0.y * w0.y + a0.z * w0.z + a0.w * w0.w
                   + a1.x * w1.x + a1.y * w1.y + a1.z * w1.z + a1.w * w1.w;
        }
        #pragma unroll
        for (int rit = 0; rit < 4; rit++) {
            #pragma unroll
            for (int o = 16; o; o >>= 1)
                p[rit] += __shfl_down_sync(0xFFFFFFFFu, p[rit], o);
        }
        if (lane == 0) {
            dst[base + 0] = p[0];
            dst[base + 1] = p[1];
            dst[base + 2] = p[2];
            dst[base + 3] = p[3];
        }
    } else {
        // UT[e, pidx(d)] = round(U[d, e]) via 64x64 smem transpose
        int tb = bid - ROW_BLOCKS;              // 0..15
        int d0 = (tb & 3) * 64, e0 = (tb >> 2) * 64;
        #pragma unroll
        for (int i = 0; i < 16; i++) {
            int ii = i * 256 + tid;
            int r = ii >> 6, c = ii & 63;
            tile[r][c] = rnd_tf32(U[(size_t)(d0 + r) * Dn + e0 + c]);
        }
        __syncthreads();
        #pragma unroll
        for (int i = 0; i < 16; i++) {
            int ii = i * 256 + tid;
            int r = ii >> 6, c = ii & 63;
            g_UT[(size_t)(e0 + r) * Dn + pidx(d0 + c)] = tile[c][r];
        }
    }
}

// ---------------- tf32 MMA GEMM: CTA tile 128x128, 4 warps, warp tile 64x64 ----------------
static constexpr int BM = 128, BN = 128, BK = 32, TH = 128;
static constexpr int STAGES = 3;
static constexpr int ATILE_F = BM * BK;
static constexpr int BTILE_F = BN * BK;
static constexpr uint32_t STAGE_BYTES = (ATILE_F + BTILE_F) * 4;      // 32768
static constexpr uint32_t EXTRA_OFF = STAGES * STAGE_BYTES;           // 98304
static constexpr uint32_t SMEM_BYTES = EXTRA_OFF + 1024;

__device__ __forceinline__ uint32_t smem_u32(const void* p) {
    uint32_t a;
    asm("{ .reg .u64 t; cvta.to.shared.u64 t, %1; cvt.u32.u64 %0, t; }"
        : "=r"(a) : "l"(p));
    return a;
}
__device__ __forceinline__ void cpasync16(uint32_t dst, const float* src) {
    size_t g = __cvta_generic_to_global(src);
    asm volatile("cp.async.cg.shared.global [%0], [%1], 16;" :: "r"(dst), "l"(g));
}
__device__ __forceinline__ void mma_tf32(float* c, const uint32_t* a, const uint32_t* b) {
    asm volatile(
        "mma.sync.aligned.m16n8k8.row.col.f32.tf32.tf32.f32 "
        "{%0,%1,%2,%3}, {%4,%5,%6,%7}, {%8,%9}, {%0,%1,%2,%3};"
        : "+f"(c[0]), "+f"(c[1]), "+f"(c[2]), "+f"(c[3])
        : "r"(a[0]), "r"(a[1]), "r"(a[2]), "r"(a[3]), "r"(b[0]), "r"(b[1]));
}

// MODE 0: grid (128,2,1): P = round(head) @ UT      (A raw+CVT, B permuted)
// MODE 1: grid (16,16,8): out = P @ round(dep)^T +… (A permuted, B raw+CVT)
template <int MODE>
__global__ void __launch_bounds__(TH, 2)
gemm_kernel(float* __restrict__ out, const float* __restrict__ eb,
            const float* __restrict__ head, const float* __restrict__ dep) {
    extern __shared__ float sm[];
    const uint32_t sb = smem_u32(sm);

    const int tid = threadIdx.x;
    const int w = tid >> 5, lane = tid & 31;
    const int wm = w >> 1;
    const int wn = w & 1;
    const int x = blockIdx.x, y = blockIdx.y, z = blockIdx.z;

    const float *Ag, *Bg;
    size_t aRow0, bRow0;
    if (MODE == 0) { Ag = head;  Bg = g_UT; aRow0 = (size_t)x * BM; bRow0 = (size_t)y * BN; }
    else           { Ag = g_P;   Bg = dep;  aRow0 = (size_t)z * Sn + (size_t)x * BM;
                                             bRow0 = (size_t)z * Sn + (size_t)y * BN; }

    if (MODE == 1) {
        float* sex = sm + EXTRA_OFF / 4;
        sex[tid]       = g_hs[aRow0 + tid];
        sex[128 + tid] = g_ds[bRow0 + tid];
    }

    auto load_chunk = [&](int kt) {
        int stg = kt % STAGES;
        uint32_t baseA = sb + (uint32_t)stg * STAGE_BYTES;
        uint32_t baseB = baseA + ATILE_F * 4;
        int k0 = kt * BK;
        #pragma unroll
        for (int i = 0; i < 8; i++) {
            int cid = i * 128 + tid;
            int r = cid >> 3, c4 = cid & 7;
            uint32_t soff = (uint32_t)(r * 128 + (((2 * c4) ^ ((r & 3) << 2)) << 3));
            cpasync16(baseA + soff, Ag + (aRow0 + r) * Dn + k0 + c4 * 4);
        }
        #pragma unroll
        for (int i = 0; i < 8; i++) {
            int cid = i * 128 + tid;
            int r = cid >> 3, c4 = cid & 7;
            uint32_t soff = (uint32_t)(r * 128 + (((2 * c4) ^ ((r & 3) << 2)) << 3));
            cpasync16(baseB + soff, Bg + (bRow0 + r) * Dn + k0 + c4 * 4);
        }
        asm volatile("cp.async.commit_group;" ::: "memory");
    };

    float acc[4][8][4];
    #pragma unroll
    for (int i = 0; i < 4; i++)
        #pragma unroll
        for (int j = 0; j < 8; j++)
            #pragma unroll
            for (int t = 0; t < 4; t++) acc[i][j][t] = 0.f;

    load_chunk(0);
    load_chunk(1);

    const int rA = wm * 64 + (lane >> 2);
    const int rB = wn * 64 + (lane >> 2);
    const int kq = lane & 3;
    const uint32_t sw = ((uint32_t)((lane >> 2) & 3)) << 2;

    #pragma unroll 1
    for (int kt = 0; kt < 8; kt++) {
        if (kt == 7) { asm volatile("cp.async.wait_group 0;" ::: "memory"); }
        else         { asm volatile("cp.async.wait_group 1;" ::: "memory"); }
        __syncthreads();
        if (kt + 2 < 8) load_chunk(kt + 2);

        int stg = kt % STAGES;
        uint32_t baseA = sb + (uint32_t)stg * STAGE_BYTES;
        uint32_t baseB = baseA + ATILE_F * 4;

        #pragma unroll
        for (int ks = 0; ks < 4; ks++) {
            // raw-layout offsets (elements k=ks*8+kq and k+4)
            uint32_t off0 = ((((uint32_t)(4 * ks)) ^ sw) << 3) + kq * 4;
            uint32_t off2 = ((((uint32_t)(4 * ks + 2)) ^ sw) << 3) + kq * 4;
            // permuted-layout offset (LDS.64 pair)
            uint32_t slotOff = (((uint32_t)(ks * 4 + kq)) ^ sw) << 3;

            uint32_t a[4][4];
            if (MODE == 0) {
                #pragma unroll
                for (int i = 0; i < 4; i++) {
                    uint32_t rb = baseA + (uint32_t)(rA + i * 16) * 128;
                    float x0, x1, x2, x3;
                    asm volatile("ld.shared.f32 %0, [%1];" : "=f"(x0) : "r"(rb + off0));
                    asm volatile("ld.shared.f32 %0, [%1];" : "=f"(x1) : "r"(rb + 1024 + off0));
                    asm volatile("ld.shared.f32 %0, [%1];" : "=f"(x2) : "r"(rb + off2));
                    asm volatile("ld.shared.f32 %0, [%1];" : "=f"(x3) : "r"(rb + 1024 + off2));
                    a[i][0] = f2tf(x0); a[i][1] = f2tf(x1);
                    a[i][2] = f2tf(x2); a[i][3] = f2tf(x3);
                }
            } else {
                #pragma unroll
                for (int i = 0; i < 4; i++) {
                    uint32_t ad0 = baseA + (uint32_t)(rA + i * 16) * 128 + slotOff;
                    float2 f0, f1;
                    asm volatile("ld.shared.v2.f32 {%0,%1}, [%2];"
                                 : "=f"(f0.x), "=f"(f0.y) : "r"(ad0));
                    asm volatile("ld.shared.v2.f32 {%0,%1}, [%2];"
                                 : "=f"(f1.x), "=f"(f1.y) : "r"(ad0 + 8 * 128));
                    a[i][0] = __float_as_uint(f0.x);
                    a[i][2] = __float_as_uint(f0.y);
                    a[i][1] = __float_as_uint(f1.x);
                    a[i][3] = __float_as_uint(f1.y);
                }
            }

            uint32_t b[8][2];
            if (MODE == 0) {
                #pragma unroll
                for (int j = 0; j < 8; j++) {
                    uint32_t bd = baseB + (uint32_t)(rB + j * 8) * 128 + slotOff;
                    float2 f;
                    asm volatile("ld.shared.v2.f32 {%0,%1}, [%2];"
                                 : "=f"(f.x), "=f"(f.y) : "r"(bd));
                    b[j][0] = __float_as_uint(f.x);
                    b[j][1] = __float_as_uint(f.y);
                }
            } else {
                #pragma unroll
                for (int j = 0; j < 8; j++) {
                    uint32_t rb = baseB + (uint32_t)(rB + j * 8) * 128;
                    float f0, f1;
                    asm volatile("ld.shared.f32 %0, [%1];" : "=f"(f0) : "r"(rb + off0));
                    asm volatile("ld.shared.f32 %0, [%1];" : "=f"(f1) : "r"(rb + off2));
                    b[j][0] = f2tf(f0);
                    b[j][1] = f2tf(f1);
                }
            }
            #pragma unroll
            for (int i = 0; i < 4; i++)
                #pragma unroll
                for (int j = 0; j < 8; j++)
                    mma_tf32(acc[i][j], a[i], b[j]);
        }
    }

    if (MODE == 0) {
        size_t col0 = (size_t)y * BN;
        #pragma unroll
        for (int i = 0; i < 4; i++) {
            size_t gr = (aRow0 + wm * 64 + i * 16 + (lane >> 2)) * (size_t)Dn + col0;
            #pragma unroll
            for (int j = 0; j < 8; j++) {
                int c = wn * 64 + j * 8 + (lane & 3) * 2;
                int p0 = pidx(c), p1 = pidx(c + 1);
                g_P[gr + p0]          = rnd_tf32(acc[i][j][0]);
                g_P[gr + p1]          = rnd_tf32(acc[i][j][1]);
                g_P[gr + 8 * Dn + p0] = rnd_tf32(acc[i][j][2]);
                g_P[gr + 8 * Dn + p1] = rnd_tf32(acc[i][j][3]);
            }
        }
    } else {
        float bias = __ldg(eb);
        const float* shs = sm + EXTRA_OFF / 4;
        const float* sds = shs + 128;
        #pragma unroll
        for (int i = 0; i < 4; i++) {
            int rl = wm * 64 + i * 16 + (lane >> 2);
            float hs0 = shs[rl] + bias;
            float hs1 = shs[rl + 8] + bias;
            size_t gr0 = (aRow0 + rl) * (size_t)Sn + (size_t)y * BN;
            #pragma unroll
            for (int j = 0; j < 8; j++) {
                int c = wn * 64 + j * 8 + (lane & 3) * 2;
                float d0 = sds[c], d1 = sds[c + 1];
                *(float2*)(out + gr0 + c) =
                    make_float2(acc[i][j][0] + hs0 + d0, acc[i][j][1] + hs0 + d1);
                *(float2*)(out + gr0 + 8 * (size_t)Sn + c) =
                    make_float2(acc[i][j][2] + hs1 + d0, acc[i][j][3] + hs1 + d1);
            }
        }
    }
}

// ---------------- kernel_launch ----------------
extern "C" void kernel_launch(void* const* d_in, const int* in_sizes, int n_in,
                              void* d_out, int out_size) {
    const float* head = (const float*)d_in[0];
    const float* dep  = (const float*)d_in[1];
    const float* U    = (const float*)d_in[2];
    const float* W    = (const float*)d_in[3];
    const float* eb   = (const float*)d_in[4];
    float* out = (float*)d_out;
    (void)in_sizes; (void)n_in; (void)out_size;

    cudaFuncSetAttribute(gemm_kernel<0>,
                         cudaFuncAttributeMaxDynamicSharedMemorySize, SMEM_BYTES);
    cudaFuncSetAttribute(gemm_kernel<1>,
                         cudaFuncAttributeMaxDynamicSharedMemorySize, SMEM_BYTES);

    // 1) prep: hs/ds row dots (pure stream read) + UT transpose
    prep_all<<<ROW_BLOCKS + UT_BLOCKS, 256>>>(head, dep, U, W);
    // 2) stage-1: P = round(head) @ UT
    gemm_kernel<0><<<dim3(BM, 2, 1), TH, SMEM_BYTES>>>(out, eb, head, dep);
    // 3) stage-2: out[b] = P[b] @ round(dep[b])^T + hs + ds + bias
    gemm_kernel<1><<<dim3(Sn / BM, Sn / BN, Bn), TH, SMEM_BYTES>>>(out, eb, head, dep);
}

// round 13
// speedup vs baseline: 1.6120x; 1.6120x over previous
#include <cuda_runtime.h>
#include <cstdint>

// Problem constants: B=8, S=2048, D=256
static constexpr int Bn = 8;
static constexpr int Sn = 2048;
static constexpr int Dn = 256;
static constexpr int MROWS = Bn * Sn;   // 16384

// k-dim permutation within each 8-col group (A path): q -> ((q&3)<<1)|(q>>2)
__host__ __device__ __forceinline__ int pidx(int c) {
    return (c & ~7) | (((c & 3) << 1) | ((c >> 2) & 1));
}

// ---------------- device scratch (no cudaMalloc allowed) ----------------
__device__ __align__(16) float g_P[MROWS * Dn];     // head @ U, tf32-rounded, k-permuted
// depB: tile-blocked vector layout. tile = (batch*16 + ntile)*8 + ktile, 4096 floats.
// vector (v, slotpos): v = n-vector-row (0..63), slotpos = swizzled k-slot (0..15).
// content = {B[n][k], B[n][k+4], B[n+8][k], B[n+8][k+4]},
//   n = (v>>3)*16 + (v&7),  slot = slotpos ^ ((v&1)<<2),  k = (slot>>2)*8 + (slot&3)  (+ktile*32)
__device__ __align__(16) float g_depB[MROWS * Dn];
__device__ __align__(16) float g_UT[Dn * Dn];       // U^T, tf32-rounded, k-permuted
__device__ float g_hs[MROWS];
__device__ float g_ds[MROWS];

__device__ __forceinline__ float rnd_tf32(float x) {
    uint32_t r; asm("cvt.rna.tf32.f32 %0, %1;" : "=r"(r) : "f"(x));
    return __uint_as_float(r);
}
__device__ __forceinline__ uint32_t f2tf(float x) {
    uint32_t r; asm("cvt.rna.tf32.f32 %0, %1;" : "=r"(r) : "f"(x));
    return r;
}

// ---------------- prep: hs (head dots) | dep staging->ds+depB | UT transpose ----------------
static constexpr int HEAD_BLOCKS = MROWS / 16;   // 1024
static constexpr int DEP_BLOCKS = MROWS / 16;    // 1024
static constexpr int UT_BLOCKS = 16;

__global__ void __launch_bounds__(256) prep_all(const float* __restrict__ head,
                                                const float* __restrict__ dep,
                                                const float* __restrict__ U,
                                                const float* __restrict__ W) {
    __shared__ float sbuf[16 * 264];   // dep staging (16 rows x 264) / UT tile alias
    int bid = blockIdx.x;
    int tid = threadIdx.x, w = tid >> 5, lane = tid & 31;

    if (bid < HEAD_BLOCKS) {
        // ---- head rows: hs dots only (2 rows/warp) ----
        int base = bid * 16;
        float4 w0 = *(const float4*)(W + lane * 8);
        float4 w1 = *(const float4*)(W + lane * 8 + 4);
        #pragma unroll
        for (int rit = 0; rit < 2; rit++) {
            int rr = base + w * 2 + rit;
            const float* sp = head + (size_t)rr * Dn + lane * 8;
            float4 a0 = *(const float4*)sp;
            float4 a1 = *(const float4*)(sp + 4);
            float p = a0.x * w0.x + a0.y * w0.y + a0.z * w0.z + a0.w * w0.w
                    + a1.x * w1.x + a1.y * w1.y + a1.z * w1.z + a1.w * w1.w;
            #pragma unroll
            for (int o = 16; o; o >>= 1) p += __shfl_down_sync(0xFFFFFFFFu, p, o);
            if (lane == 0) g_hs[rr] = p;
        }
        return;
    }

    if (bid < HEAD_BLOCKS + DEP_BLOCKS) {
        // ---- dep rows: stage 16 raw rows, compute ds, emit rounded vectors ----
        int rr0 = (bid - HEAD_BLOCKS) * 16;     // 16-aligned dep row base
        float (*s)[264] = (float(*)[264])sbuf;
        #pragma unroll
        for (int i = 0; i < 16; i++)
            s[i][tid] = dep[(size_t)(rr0 + i) * Dn + tid];
        __syncthreads();

        // ds: warp w handles rows 2w, 2w+1 (raw values)
        {
            const float* wd = W + Dn;
            float wv[8];
            #pragma unroll
            for (int m = 0; m < 8; m++) wv[m] = __ldg(wd + lane + 32 * m);
            #pragma unroll
            for (int rw = 0; rw < 2; rw++) {
                int row = w * 2 + rw;
                float p = 0.f;
                #pragma unroll
                for (int m = 0; m < 8; m++) p += s[row][lane + 32 * m] * wv[m];
                #pragma unroll
                for (int o = 16; o; o >>= 1) p += __shfl_down_sync(0xFFFFFFFFu, p, o);
                if (lane == 0) g_ds[rr0 + row] = p;
            }
        }

        // vector emit: 1024 vectors (8 ktiles x 8 vrows x 16 slots), coalesced STG.128
        int z = rr0 / Sn;
        int nb = rr0 % Sn;
        int ytile = nb >> 7;
        int nn0 = nb & 127;
        int VB = (nn0 >> 4) * 8;                 // v-row base within tile
        size_t tb0 = ((size_t)(z * 16 + ytile)) * 8 * 4096;
        #pragma unroll
        for (int it = 0; it < 4; it++) {
            int vec = it * 256 + tid;            // 0..1023
            int kt = vec >> 7;
            int u = vec & 127;
            int vr = u >> 4;                     // 0..7
            int slotpos = u & 15;
            int slot = slotpos ^ ((vr & 1) << 2);
            int k = kt * 32 + (slot >> 2) * 8 + (slot & 3);
            float4 o = make_float4(rnd_tf32(s[vr][k]),     rnd_tf32(s[vr][k + 4]),
                                   rnd_tf32(s[vr + 8][k]), rnd_tf32(s[vr + 8][k + 4]));
            *(float4*)(g_depB + tb0 + (size_t)kt * 4096 + ((VB + vr) * 16 + slotpos) * 4) = o;
        }
        return;
    }

    // ---- UT: UT[e, pidx(d)] = round(U[d, e]) via 64x64 smem transpose ----
    {
        float (*tile)[65] = (float(*)[65])sbuf;  // 64*65=4160 <= 16*264
        int tb = bid - HEAD_BLOCKS - DEP_BLOCKS;
        int d0 = (tb & 3) * 64, e0 = (tb >> 2) * 64;
        #pragma unroll
        for (int i = 0; i < 16; i++) {
            int ii = i * 256 + tid;
            int r = ii >> 6, c = ii & 63;
            tile[r][c] = rnd_tf32(U[(size_t)(d0 + r) * Dn + e0 + c]);
        }
        __syncthreads();
        #pragma unroll
        for (int i = 0; i < 16; i++) {
            int ii = i * 256 + tid;
            int r = ii >> 6, c = ii & 63;
            g_UT[(size_t)(e0 + r) * Dn + pidx(d0 + c)] = tile[c][r];
        }
    }
}

// ---------------- tf32 MMA GEMM: CTA tile 128x128, 4 warps, warp tile 64x64 ----------------
static constexpr int BM = 128, BN = 128, BK = 32, TH = 128;
static constexpr int STAGES = 3;
static constexpr int ATILE_F = BM * BK;
static constexpr int BTILE_F = BN * BK;
static constexpr uint32_t STAGE_BYTES = (ATILE_F + BTILE_F) * 4;      // 32768
static constexpr uint32_t EXTRA_OFF = STAGES * STAGE_BYTES;           // 98304
static constexpr uint32_t SMEM_BYTES = EXTRA_OFF + 1024;

__device__ __forceinline__ uint32_t smem_u32(const void* p) {
    uint32_t a;
    asm("{ .reg .u64 t; cvta.to.shared.u64 t, %1; cvt.u32.u64 %0, t; }"
        : "=r"(a) : "l"(p));
    return a;
}
__device__ __forceinline__ void cpasync16(uint32_t dst, const float* src) {
    size_t g = __cvta_generic_to_global(src);
    asm volatile("cp.async.cg.shared.global [%0], [%1], 16;" :: "r"(dst), "l"(g));
}
__device__ __forceinline__ void mma_tf32(float* c, const uint32_t* a, const uint32_t* b) {
    asm volatile(
        "mma.sync.aligned.m16n8k8.row.col.f32.tf32.tf32.f32 "
        "{%0,%1,%2,%3}, {%4,%5,%6,%7}, {%8,%9}, {%0,%1,%2,%3};"
        : "+f"(c[0]), "+f"(c[1]), "+f"(c[2]), "+f"(c[3])
        : "r"(a[0]), "r"(a[1]), "r"(a[2]), "r"(a[3]), "r"(b[0]), "r"(b[1]));
}

// MODE 0: grid (128,2,1): P = round(head) @ UT   (A raw+CVT, B permuted LDS.64)
// MODE 1: grid (16,16,8): out = P @ depB^T + hs + ds + b  (A permuted LDS.64, B vector LDS.128)
template <int MODE>
__global__ void __launch_bounds__(TH, 2)
gemm_kernel(float* __restrict__ out, const float* __restrict__ eb,
            const float* __restrict__ head) {
    extern __shared__ float sm[];
    const uint32_t sb = smem_u32(sm);

    const int tid = threadIdx.x;
    const int w = tid >> 5, lane = tid & 31;
    const int wm = w >> 1;
    const int wn = w & 1;
    const int x = blockIdx.x, y = blockIdx.y, z = blockIdx.z;

    const float* Ag;
    size_t aRow0;
    const float* BtVec = nullptr;    // MODE 1 tile-blocked B
    const float* Bg = nullptr;       // MODE 0 row-major B
    size_t bRow0 = 0;
    if (MODE == 0) {
        Ag = head; aRow0 = (size_t)x * BM;
        Bg = g_UT; bRow0 = (size_t)y * BN;
    } else {
        Ag = g_P;  aRow0 = (size_t)z * Sn + (size_t)x * BM;
        BtVec = g_depB + ((size_t)(z * 16 + y)) * 8 * 4096;
    }

    if (MODE == 1) {
        float* sex = sm + EXTRA_OFF / 4;
        sex[tid]       = g_hs[aRow0 + tid];
        sex[128 + tid] = g_ds[(size_t)z * Sn + (size_t)y * BN + tid];
    }

    auto load_chunk = [&](int kt) {
        int stg = kt % STAGES;
        uint32_t baseA = sb + (uint32_t)stg * STAGE_BYTES;
        uint32_t baseB = baseA + ATILE_F * 4;
        int k0 = kt * BK;
        #pragma unroll
        for (int i = 0; i < 8; i++) {
            int cid = i * 128 + tid;
            int r = cid >> 3, c4 = cid & 7;
            uint32_t soff = (uint32_t)(r * 128 + (((2 * c4) ^ ((r & 3) << 2)) << 3));
            cpasync16(baseA + soff, Ag + (aRow0 + r) * Dn + k0 + c4 * 4);
        }
        if (MODE == 0) {
            #pragma unroll
            for (int i = 0; i < 8; i++) {
                int cid = i * 128 + tid;
                int r = cid >> 3, c4 = cid & 7;
                uint32_t soff = (uint32_t)(r * 128 + (((2 * c4) ^ ((r & 3) << 2)) << 3));
                cpasync16(baseB + soff, Bg + (bRow0 + r) * Dn + k0 + c4 * 4);
            }
        } else {
            // contiguous 16KB vector tile
            #pragma unroll
            for (int i = 0; i < 8; i++) {
                int cid = i * 128 + tid;
                cpasync16(baseB + (uint32_t)cid * 16, BtVec + (size_t)kt * 4096 + cid * 4);
            }
        }
        asm volatile("cp.async.commit_group;" ::: "memory");
    };

    float acc[4][8][4];
    #pragma unroll
    for (int i = 0; i < 4; i++)
        #pragma unroll
        for (int j = 0; j < 8; j++)
            #pragma unroll
            for (int t = 0; t < 4; t++) acc[i][j][t] = 0.f;

    load_chunk(0);
    load_chunk(1);

    const int rA = wm * 64 + (lane >> 2);
    const int rB = wn * 64 + (lane >> 2);   // MODE 0 B row base
    const int rq = lane >> 2;               // 0..7
    const int kq = lane & 3;
    const uint32_t sw = ((uint32_t)(rq & 3)) << 2;

    #pragma unroll 1
    for (int kt = 0; kt < 8; kt++) {
        if (kt == 7) { asm volatile("cp.async.wait_group 0;" ::: "memory"); }
        else         { asm volatile("cp.async.wait_group 1;" ::: "memory"); }
        __syncthreads();
        if (kt + 2 < 8) load_chunk(kt + 2);

        int stg = kt % STAGES;
        uint32_t baseA = sb + (uint32_t)stg * STAGE_BYTES;
        uint32_t baseB = baseA + ATILE_F * 4;

        #pragma unroll
        for (int ks = 0; ks < 4; ks++) {
            uint32_t a[4][4];
            if (MODE == 0) {
                uint32_t off0 = ((((uint32_t)(4 * ks)) ^ sw) << 3) + kq * 4;
                uint32_t off2 = ((((uint32_t)(4 * ks + 2)) ^ sw) << 3) + kq * 4;
                #pragma unroll
                for (int i = 0; i < 4; i++) {
                    uint32_t rb = baseA + (uint32_t)(rA + i * 16) * 128;
                    float x0, x1, x2, x3;
                    asm volatile("ld.shared.f32 %0, [%1];" : "=f"(x0) : "r"(rb + off0));
                    asm volatile("ld.shared.f32 %0, [%1];" : "=f"(x1) : "r"(rb + 1024 + off0));
                    asm volatile("ld.shared.f32 %0, [%1];" : "=f"(x2) : "r"(rb + off2));
                    asm volatile("ld.shared.f32 %0, [%1];" : "=f"(x3) : "r"(rb + 1024 + off2));
                    a[i][0] = f2tf(x0); a[i][1] = f2tf(x1);
                    a[i][2] = f2tf(x2); a[i][3] = f2tf(x3);
                }
            } else {
                uint32_t slotOff = (((uint32_t)(ks * 4 + kq)) ^ sw) << 3;
                #pragma unroll
                for (int i = 0; i < 4; i++) {
                    uint32_t ad0 = baseA + (uint32_t)(rA + i * 16) * 128 + slotOff;
                    float2 f0, f1;
                    asm volatile("ld.shared.v2.f32 {%0,%1}, [%2];"
                                 : "=f"(f0.x), "=f"(f0.y) : "r"(ad0));
                    asm volatile("ld.shared.v2.f32 {%0,%1}, [%2];"
                                 : "=f"(f1.x), "=f"(f1.y) : "r"(ad0 + 8 * 128));
                    a[i][0] = __float_as_uint(f0.x);
                    a[i][2] = __float_as_uint(f0.y);
                    a[i][1] = __float_as_uint(f1.x);
                    a[i][3] = __float_as_uint(f1.y);
                }
            }

            uint32_t b[8][2];
            if (MODE == 0) {
                uint32_t slotOff = (((uint32_t)(ks * 4 + kq)) ^ sw) << 3;
                #pragma unroll
                for (int j = 0; j < 8; j++) {
                    uint32_t bd = baseB + (uint32_t)(rB + j * 8) * 128 + slotOff;
                    float2 f;
                    asm volatile("ld.shared.v2.f32 {%0,%1}, [%2];"
                                 : "=f"(f.x), "=f"(f.y) : "r"(bd));
                    b[j][0] = __float_as_uint(f.x);
                    b[j][1] = __float_as_uint(f.y);
                }
            } else {
                // vector path: one LDS.128 per j-pair
                uint32_t slotpos = ((uint32_t)(ks * 4 + kq)) ^ (((uint32_t)rq & 1) << 2);
                #pragma unroll
                for (int jp = 0; jp < 4; jp++) {
                    uint32_t v = (uint32_t)((wn * 4 + jp) * 8 + rq);
                    uint32_t bd = baseB + (v * 16 + slotpos) * 16;
                    float4 f;
                    asm volatile("ld.shared.v4.f32 {%0,%1,%2,%3}, [%4];"
                                 : "=f"(f.x), "=f"(f.y), "=f"(f.z), "=f"(f.w) : "r"(bd));
                    b[2 * jp][0]     = __float_as_uint(f.x);
                    b[2 * jp][1]     = __float_as_uint(f.y);
                    b[2 * jp + 1][0] = __float_as_uint(f.z);
                    b[2 * jp + 1][1] = __float_as_uint(f.w);
                }
            }
            #pragma unroll
            for (int i = 0; i < 4; i++)
                #pragma unroll
                for (int j = 0; j < 8; j++)
                    mma_tf32(acc[i][j], a[i], b[j]);
        }
    }

    if (MODE == 0) {
        size_t col0 = (size_t)y * BN;
        #pragma unroll
        for (int i = 0; i < 4; i++) {
            size_t gr = (aRow0 + wm * 64 + i * 16 + (lane >> 2)) * (size_t)Dn + col0;
            #pragma unroll
            for (int j = 0; j < 8; j++) {
                int c = wn * 64 + j * 8 + (lane & 3) * 2;
                int p0 = pidx(c), p1 = pidx(c + 1);
                g_P[gr + p0]          = rnd_tf32(acc[i][j][0]);
                g_P[gr + p1]          = rnd_tf32(acc[i][j][1]);
                g_P[gr + 8 * Dn + p0] = rnd_tf32(acc[i][j][2]);
                g_P[gr + 8 * Dn + p1] = rnd_tf32(acc[i][j][3]);
            }
        }
    } else {
        float bias = __ldg(eb);
        const float* shs = sm + EXTRA_OFF / 4;
        const float* sds = shs + 128;
        #pragma unroll
        for (int i = 0; i < 4; i++) {
            int rl = wm * 64 + i * 16 + (lane >> 2);
            float hs0 = shs[rl] + bias;
            float hs1 = shs[rl + 8] + bias;
            size_t gr0 = (aRow0 + rl) * (size_t)Sn + (size_t)y * BN;
            #pragma unroll
            for (int j = 0; j < 8; j++) {
                int c = wn * 64 + j * 8 + (lane & 3) * 2;
                float d0 = sds[c], d1 = sds[c + 1];
                *(float2*)(out + gr0 + c) =
                    make_float2(acc[i][j][0] + hs0 + d0, acc[i][j][1] + hs0 + d1);
                *(float2*)(out + gr0 + 8 * (size_t)Sn + c) =
                    make_float2(acc[i][j][2] + hs1 + d0, acc[i][j][3] + hs1 + d1);
            }
        }
    }
}

// ---------------- kernel_launch ----------------
extern "C" void kernel_launch(void* const* d_in, const int* in_sizes, int n_in,
                              void* d_out, int out_size) {
    const float* head = (const float*)d_in[0];
    const float* dep  = (const float*)d_in[1];
    const float* U    = (const float*)d_in[2];
    const float* W    = (const float*)d_in[3];
    const float* eb   = (const float*)d_in[4];
    float* out = (float*)d_out;
    (void)in_sizes; (void)n_in; (void)out_size;

    cudaFuncSetAttribute(gemm_kernel<0>,
                         cudaFuncAttributeMaxDynamicSharedMemorySize, SMEM_BYTES);
    cudaFuncSetAttribute(gemm_kernel<1>,
                         cudaFuncAttributeMaxDynamicSharedMemorySize, SMEM_BYTES);

    // 1) prep: hs dots | dep -> ds + vector-layout depB | UT transpose
    prep_all<<<HEAD_BLOCKS + DEP_BLOCKS + UT_BLOCKS, 256>>>(head, dep, U, W);
    // 2) stage-1: P = round(head) @ UT
    gemm_kernel<0><<<dim3(BM, 2, 1), TH, SMEM_BYTES>>>(out, eb, head);
    // 3) stage-2: out[b] = P[b] @ dep[b]^T + hs + ds + bias
    gemm_kernel<1><<<dim3(Sn / BM, Sn / BN, Bn), TH, SMEM_BYTES>>>(out, eb, head);
}

// round 14
// speedup vs baseline: 2.5588x; 1.5874x over previous
#include <cuda_runtime.h>
#include <cuda_fp16.h>
#include <cstdint>

// Problem constants: B=8, S=2048, D=256
static constexpr int Bn = 8;
static constexpr int Sn = 2048;
static constexpr int Dn = 256;
static constexpr int MROWS = Bn * Sn;   // 16384

// ---------------- device scratch (no cudaMalloc allowed) ----------------
// Unified fp16 vector layout: tensors are split into (128-row x 64-k) tiles of
// 16 KB. Within a tile, vector (m,q,slotpos) [m=rowblock/16, q=row%16(<8),
// slotpos = (s*4+kq)^((q&1)<<2), k = s*16+kq*2] holds 8 halves:
//   {T[r][k],T[r][k+1], T[r+8][k],T[r+8][k+1], T[r][k+8],T[r][k+9], T[r+8][k+8],T[r+8][k+9]}
// where r = 16m+q. One LDS.128 = one m16n8k16 A fragment; B fragments for
// columns (n, n+8) come from the same vector by register renaming.
__device__ __align__(16) __half g_headH[MROWS * Dn];
__device__ __align__(16) __half g_depH [MROWS * Dn];
__device__ __align__(16) __half g_Ph   [MROWS * Dn];
__device__ __align__(16) __half g_UTH  [Dn * Dn];
__device__ float g_hs[MROWS];
__device__ float g_ds[MROWS];

static constexpr int TILE_H = 8192;     // halves per (128x64) tile

__device__ __forceinline__ uint32_t pack2(float lo, float hi) {
    __half2 h = __floats2half2_rn(lo, hi);
    return *(uint32_t*)&h;
}

// ---------------- prep: head->hs+headH | dep->ds+depH | U->UTH ----------------
static constexpr int HEAD_BLOCKS = MROWS / 16;   // 1024
static constexpr int DEP_BLOCKS = MROWS / 16;    // 1024
static constexpr int UT_BLOCKS = 16;

__global__ void __launch_bounds__(256) prep_all(const float* __restrict__ head,
                                                const float* __restrict__ dep,
                                                const float* __restrict__ U,
                                                const float* __restrict__ W) {
    __shared__ float s[16][264];
    int bid = blockIdx.x;
    int tid = threadIdx.x, w = tid >> 5, lane = tid & 31;

    const float* src;
    __half* dstH;
    float* dotDst = nullptr;
    const float* wvp = nullptr;
    int r0;            // 16-row base within the tensor's row space

    if (bid < HEAD_BLOCKS) {
        src = head; dstH = g_headH; dotDst = g_hs; wvp = W;
        r0 = bid * 16;
        #pragma unroll
        for (int i = 0; i < 16; i++)
            s[i][tid] = src[(size_t)(r0 + i) * Dn + tid];
        __syncthreads();
    } else if (bid < HEAD_BLOCKS + DEP_BLOCKS) {
        src = dep; dstH = g_depH; dotDst = g_ds; wvp = W + Dn;
        r0 = (bid - HEAD_BLOCKS) * 16;
        #pragma unroll
        for (int i = 0; i < 16; i++)
            s[i][tid] = src[(size_t)(r0 + i) * Dn + tid];
        __syncthreads();
    } else {
        // UT rows e, cols d: s[e'][d] = U[d][e0+e']
        int tb = bid - HEAD_BLOCKS - DEP_BLOCKS;
        r0 = tb * 16;
        dstH = g_UTH;
        #pragma unroll
        for (int i = 0; i < 16; i++) {
            int d = i * 16 + (tid >> 4);
            int e = tid & 15;
            s[e][d] = U[(size_t)d * Dn + r0 + e];
        }
        __syncthreads();
    }

    // row dots (head/dep only): warp w handles rows 2w, 2w+1
    if (dotDst) {
        float wv[8];
        #pragma unroll
        for (int m = 0; m < 8; m++) wv[m] = __ldg(wvp + lane + 32 * m);
        #pragma unroll
        for (int rw = 0; rw < 2; rw++) {
            int row = w * 2 + rw;
            float p = 0.f;
            #pragma unroll
            for (int m = 0; m < 8; m++) p += s[row][lane + 32 * m] * wv[m];
            #pragma unroll
            for (int o = 16; o; o >>= 1) p += __shfl_down_sync(0xFFFFFFFFu, p, o);
            if (lane == 0) dotDst[r0 + row] = p;
        }
    }

    // emit 512 vectors (4 kc x 8 q x 16 slotpos), 2 per thread, coalesced STG.128
    int rowtile = r0 >> 7;
    int m = (r0 & 127) >> 4;
    #pragma unroll
    for (int it = 0; it < 2; it++) {
        int v = it * 256 + tid;                 // 0..511
        int kc = v >> 7;
        int u = v & 127;
        int q = u >> 4;                         // 0..7
        int slotpos = u & 15;
        int slot = slotpos ^ ((q & 1) << 2);
        int k = kc * 64 + (slot >> 2) * 16 + (slot & 3) * 2;
        uint4 o;
        o.x = pack2(s[q][k],         s[q][k + 1]);
        o.y = pack2(s[q + 8][k],     s[q + 8][k + 1]);
        o.z = pack2(s[q][k + 8],     s[q][k + 9]);
        o.w = pack2(s[q + 8][k + 8], s[q + 8][k + 9]);
        size_t off = ((size_t)(rowtile * 4 + kc)) * TILE_H
                   + ((m * 8 + q) * 16 + slotpos) * 8;
        *(uint4*)(dstH + off) = o;
    }
}

// ---------------- fp16 MMA GEMM: CTA 128x128, 4 warps, warp tile 64x64, BK=64 ----------------
static constexpr int BM = 128, BN = 128, TH = 128;
static constexpr int STAGES = 3;
static constexpr uint32_t TILE_BYTES = 16384;                 // 128x64 fp16
static constexpr uint32_t STAGE_BYTES = 2 * TILE_BYTES;       // A + B
static constexpr uint32_t EXTRA_OFF = STAGES * STAGE_BYTES;   // 98304
static constexpr uint32_t SMEM_BYTES = EXTRA_OFF + 1024;

__device__ __forceinline__ uint32_t smem_u32(const void* p) {
    uint32_t a;
    asm("{ .reg .u64 t; cvta.to.shared.u64 t, %1; cvt.u32.u64 %0, t; }"
        : "=r"(a) : "l"(p));
    return a;
}
__device__ __forceinline__ void cpasync16(uint32_t dst, const void* src) {
    size_t g = __cvta_generic_to_global(src);
    asm volatile("cp.async.cg.shared.global [%0], [%1], 16;" :: "r"(dst), "l"(g));
}
__device__ __forceinline__ void mma_f16(float* c, const uint32_t* a, const uint32_t* b) {
    asm volatile(
        "mma.sync.aligned.m16n8k16.row.col.f32.f16.f16.f32 "
        "{%0,%1,%2,%3}, {%4,%5,%6,%7}, {%8,%9}, {%0,%1,%2,%3};"
        : "+f"(c[0]), "+f"(c[1]), "+f"(c[2]), "+f"(c[3])
        : "r"(a[0]), "r"(a[1]), "r"(a[2]), "r"(a[3]), "r"(b[0]), "r"(b[1]));
}

// MODE 0: grid (128,2,1): Ph = headH @ UTH^T   (writes fp16 vector layout)
// MODE 1: grid (16,16,8): out = Ph @ depH^T + hs + ds + bias
template <int MODE>
__global__ void __launch_bounds__(TH, 2)
gemm_kernel(float* __restrict__ out, const float* __restrict__ eb) {
    extern __shared__ float sm[];
    const uint32_t sb = smem_u32(sm);

    const int tid = threadIdx.x;
    const int w = tid >> 5, lane = tid & 31;
    const int wm = w >> 1;          // 0..1 (M warp: 64 rows)
    const int wn = w & 1;           // 0..1 (N warp: 64 cols)
    const int x = blockIdx.x, y = blockIdx.y, z = blockIdx.z;

    const __half *Atile, *Btile;
    if (MODE == 0) {
        Atile = g_headH + (size_t)x * 4 * TILE_H;
        Btile = g_UTH   + (size_t)y * 4 * TILE_H;
    } else {
        Atile = g_Ph   + (size_t)(z * 16 + x) * 4 * TILE_H;
        Btile = g_depH + (size_t)(z * 16 + y) * 4 * TILE_H;
    }

    if (MODE == 1) {
        float* sex = sm + EXTRA_OFF / 4;
        sex[tid]       = g_hs[(size_t)z * Sn + (size_t)x * BM + tid];
        sex[128 + tid] = g_ds[(size_t)z * Sn + (size_t)y * BN + tid];
    }

    auto load_chunk = [&](int kt) {
        int stg = kt % STAGES;
        uint32_t baseA = sb + (uint32_t)stg * STAGE_BYTES;
        uint32_t baseB = baseA + TILE_BYTES;
        const __half* gA = Atile + (size_t)kt * TILE_H;
        const __half* gB = Btile + (size_t)kt * TILE_H;
        #pragma unroll
        for (int i = 0; i < 8; i++) {
            int cid = i * 128 + tid;
            cpasync16(baseA + (uint32_t)cid * 16, gA + cid * 8);
        }
        #pragma unroll
        for (int i = 0; i < 8; i++) {
            int cid = i * 128 + tid;
            cpasync16(baseB + (uint32_t)cid * 16, gB + cid * 8);
        }
        asm volatile("cp.async.commit_group;" ::: "memory");
    };

    float acc[4][8][4];
    #pragma unroll
    for (int i = 0; i < 4; i++)
        #pragma unroll
        for (int j = 0; j < 8; j++)
            #pragma unroll
            for (int t = 0; t < 4; t++) acc[i][j][t] = 0.f;

    load_chunk(0);
    load_chunk(1);

    const int rq = lane >> 2;       // 0..7
    const int kq = lane & 3;        // 0..3
    const uint32_t qoff = (uint32_t)rq * 256;
    const uint32_t xr = ((uint32_t)rq & 1) << 2;

    #pragma unroll 1
    for (int kt = 0; kt < 4; kt++) {
        if (kt == 3) { asm volatile("cp.async.wait_group 0;" ::: "memory"); }
        else         { asm volatile("cp.async.wait_group 1;" ::: "memory"); }
        __syncthreads();
        if (kt + 2 < 4) load_chunk(kt + 2);

        int stg = kt % STAGES;
        uint32_t baseA = sb + (uint32_t)stg * STAGE_BYTES;
        uint32_t baseB = baseA + TILE_BYTES;

        #pragma unroll
        for (int ks = 0; ks < 4; ks++) {
            uint32_t slotOff = ((((uint32_t)(ks * 4 + kq)) ^ xr) << 4);

            uint32_t a[4][4];
            #pragma unroll
            for (int i = 0; i < 4; i++) {
                uint32_t m = (uint32_t)(wm * 4 + i);
                uint32_t ad = baseA + m * 2048 + qoff + slotOff;
                uint4 v;
                asm volatile("ld.shared.v4.b32 {%0,%1,%2,%3}, [%4];"
                             : "=r"(v.x), "=r"(v.y), "=r"(v.z), "=r"(v.w) : "r"(ad));
                a[i][0] = v.x; a[i][1] = v.y; a[i][2] = v.z; a[i][3] = v.w;
            }

            uint32_t b[8][2];
            #pragma unroll
            for (int jp = 0; jp < 4; jp++) {
                uint32_t m = (uint32_t)(wn * 4 + jp);
                uint32_t bd = baseB + m * 2048 + qoff + slotOff;
                uint4 v;
                asm volatile("ld.shared.v4.b32 {%0,%1,%2,%3}, [%4];"
                             : "=r"(v.x), "=r"(v.y), "=r"(v.z), "=r"(v.w) : "r"(bd));
                b[2 * jp][0]     = v.x;   // (n,   k01)
                b[2 * jp][1]     = v.z;   // (n,   k89)
                b[2 * jp + 1][0] = v.y;   // (n+8, k01)
                b[2 * jp + 1][1] = v.w;   // (n+8, k89)
            }

            #pragma unroll
            for (int i = 0; i < 4; i++)
                #pragma unroll
                for (int j = 0; j < 8; j++)
                    mma_f16(acc[i][j], a[i], b[j]);
        }
    }

    if (MODE == 0) {
        // write Ph in the same fp16 vector layout
        int kc = y * 2 + wn;
        #pragma unroll
        for (int i = 0; i < 4; i++) {
            int m = wm * 4 + i;
            #pragma unroll
            for (int jp = 0; jp < 4; jp++) {
                int slotpos = (jp * 4 + kq) ^ (int)(xr >> 0);
                uint4 o;
                o.x = pack2(acc[i][2 * jp][0],     acc[i][2 * jp][1]);
                o.y = pack2(acc[i][2 * jp][2],     acc[i][2 * jp][3]);
                o.z = pack2(acc[i][2 * jp + 1][0], acc[i][2 * jp + 1][1]);
                o.w = pack2(acc[i][2 * jp + 1][2], acc[i][2 * jp + 1][3]);
                size_t off = ((size_t)(x * 4 + kc)) * TILE_H
                           + ((m * 8 + rq) * 16 + slotpos) * 8;
                *(uint4*)(g_Ph + off) = o;
            }
        }
    } else {
        float bias = __ldg(eb);
        const float* shs = sm + EXTRA_OFF / 4;
        const float* sds = shs + 128;
        size_t aRow0 = (size_t)z * Sn + (size_t)x * BM;
        #pragma unroll
        for (int i = 0; i < 4; i++) {
            int rl = wm * 64 + i * 16 + rq;
            float hs0 = shs[rl] + bias;
            float hs1 = shs[rl + 8] + bias;
            size_t gr0 = (aRow0 + rl) * (size_t)Sn + (size_t)y * BN;
            #pragma unroll
            for (int j = 0; j < 8; j++) {
                int c = wn * 64 + j * 8 + kq * 2;
                float d0 = sds[c], d1 = sds[c + 1];
                *(float2*)(out + gr0 + c) =
                    make_float2(acc[i][j][0] + hs0 + d0, acc[i][j][1] + hs0 + d1);
                *(float2*)(out + gr0 + 8 * (size_t)Sn + c) =
                    make_float2(acc[i][j][2] + hs1 + d0, acc[i][j][3] + hs1 + d1);
            }
        }
    }
}

// ---------------- kernel_launch ----------------
extern "C" void kernel_launch(void* const* d_in, const int* in_sizes, int n_in,
                              void* d_out, int out_size) {
    const float* head = (const float*)d_in[0];
    const float* dep  = (const float*)d_in[1];
    const float* U    = (const float*)d_in[2];
    const float* W    = (const float*)d_in[3];
    const float* eb   = (const float*)d_in[4];
    float* out = (float*)d_out;
    (void)in_sizes; (void)n_in; (void)out_size;

    cudaFuncSetAttribute(gemm_kernel<0>,
                         cudaFuncAttributeMaxDynamicSharedMemorySize, SMEM_BYTES);
    cudaFuncSetAttribute(gemm_kernel<1>,
                         cudaFuncAttributeMaxDynamicSharedMemorySize, SMEM_BYTES);

    // 1) prep: hs/ds dots + fp16 vector-layout headH/depH/UTH
    prep_all<<<HEAD_BLOCKS + DEP_BLOCKS + UT_BLOCKS, 256>>>(head, dep, U, W);
    // 2) stage-1: Ph = headH @ UTH^T
    gemm_kernel<0><<<dim3(MROWS / BM, 2, 1), TH, SMEM_BYTES>>>(out, eb);
    // 3) stage-2: out[b] = Ph[b] @ depH[b]^T + hs + ds + bias
    gemm_kernel<1><<<dim3(Sn / BM, Sn / BN, Bn), TH, SMEM_BYTES>>>(out, eb);
}

// round 15
// speedup vs baseline: 2.5765x; 1.0069x over previous
#include <cuda_runtime.h>
#include <cuda_fp16.h>
#include <cstdint>

// Problem constants: B=8, S=2048, D=256
static constexpr int Bn = 8;
static constexpr int Sn = 2048;
static constexpr int Dn = 256;
static constexpr int MROWS = Bn * Sn;   // 16384

// ---------------- device scratch (no cudaMalloc allowed) ----------------
// Unified fp16 vector layout: tensors are split into (128-row x 64-k) tiles of
// 16 KB. Within a tile, vector (m,q,slotpos) [m=rowblock/16, q=row%16(<8),
// slotpos = (s*4+kq)^((q&1)<<2), k = s*16+kq*2] holds 8 halves:
//   {T[r][k],T[r][k+1], T[r+8][k],T[r+8][k+1], T[r][k+8],T[r][k+9], T[r+8][k+8],T[r+8][k+9]}
// where r = 16m+q. One LDS.128 = one m16n8k16 A fragment; B fragments for
// columns (n, n+8) come from the same vector by register renaming.
__device__ __align__(16) __half g_headH[MROWS * Dn];
__device__ __align__(16) __half g_depH [MROWS * Dn];
__device__ __align__(16) __half g_Ph   [MROWS * Dn];
__device__ __align__(16) __half g_UTH  [Dn * Dn];
__device__ float g_hs[MROWS];
__device__ float g_ds[MROWS];

static constexpr int TILE_H = 8192;     // halves per (128x64) tile

__device__ __forceinline__ uint32_t pack2(float lo, float hi) {
    __half2 h = __floats2half2_rn(lo, hi);
    return *(uint32_t*)&h;
}

// ---------------- prep: head->hs+headH | dep->ds+depH | U->UTH ----------------
static constexpr int HEAD_BLOCKS = MROWS / 16;   // 1024
static constexpr int DEP_BLOCKS = MROWS / 16;    // 1024
static constexpr int UT_BLOCKS = 16;

__global__ void __launch_bounds__(256) prep_all(const float* __restrict__ head,
                                                const float* __restrict__ dep,
                                                const float* __restrict__ W,
                                                const float* __restrict__ U) {
    __shared__ float s[16][264];
    int bid = blockIdx.x;
    int tid = threadIdx.x, w = tid >> 5, lane = tid & 31;

    __half* dstH;
    float* dotDst = nullptr;
    const float* wvp = nullptr;
    int r0;            // 16-row base within the tensor's row space

    if (bid < HEAD_BLOCKS + DEP_BLOCKS) {
        bool isHead = bid < HEAD_BLOCKS;
        const float* src = isHead ? head : dep;
        dstH   = isHead ? g_headH : g_depH;
        dotDst = isHead ? g_hs : g_ds;
        wvp    = isHead ? W : (W + Dn);
        r0 = (isHead ? bid : bid - HEAD_BLOCKS) * 16;
        // vectorized staging: 1024 float4 (16 rows x 64), 4 per thread, LDG.128
        const float4* srcv = (const float4*)(src + (size_t)r0 * Dn);
        #pragma unroll
        for (int it = 0; it < 4; it++) {
            int v = it * 256 + tid;             // 0..1023
            int row = v >> 6, c4 = v & 63;
            float4 val = srcv[(size_t)row * 64 + c4];
            *(float4*)&s[row][c4 * 4] = val;
        }
        __syncthreads();
    } else {
        // UT rows e, cols d: s[e'][d] = U[d][r0+e']
        int tb = bid - HEAD_BLOCKS - DEP_BLOCKS;
        r0 = tb * 16;
        dstH = g_UTH;
        #pragma unroll
        for (int i = 0; i < 16; i++) {
            int d = i * 16 + (tid >> 4);
            int e = tid & 15;
            s[e][d] = U[(size_t)d * Dn + r0 + e];
        }
        __syncthreads();
    }

    // row dots (head/dep only): warp w handles rows 2w, 2w+1
    if (dotDst) {
        float wv[8];
        #pragma unroll
        for (int m = 0; m < 8; m++) wv[m] = __ldg(wvp + lane + 32 * m);
        #pragma unroll
        for (int rw = 0; rw < 2; rw++) {
            int row = w * 2 + rw;
            float p = 0.f;
            #pragma unroll
            for (int m = 0; m < 8; m++) p += s[row][lane + 32 * m] * wv[m];
            #pragma unroll
            for (int o = 16; o; o >>= 1) p += __shfl_down_sync(0xFFFFFFFFu, p, o);
            if (lane == 0) dotDst[r0 + row] = p;
        }
    }

    // emit 512 vectors (4 kc x 8 q x 16 slotpos), 2 per thread, coalesced STG.128
    int rowtile = r0 >> 7;
    int m = (r0 & 127) >> 4;
    #pragma unroll
    for (int it = 0; it < 2; it++) {
        int v = it * 256 + tid;                 // 0..511
        int kc = v >> 7;
        int u = v & 127;
        int q = u >> 4;                         // 0..7
        int slotpos = u & 15;
        int slot = slotpos ^ ((q & 1) << 2);
        int k = kc * 64 + (slot >> 2) * 16 + (slot & 3) * 2;
        uint4 o;
        o.x = pack2(s[q][k],         s[q][k + 1]);
        o.y = pack2(s[q + 8][k],     s[q + 8][k + 1]);
        o.z = pack2(s[q][k + 8],     s[q][k + 9]);
        o.w = pack2(s[q + 8][k + 8], s[q + 8][k + 9]);
        size_t off = ((size_t)(rowtile * 4 + kc)) * TILE_H
                   + ((m * 8 + q) * 16 + slotpos) * 8;
        *(uint4*)(dstH + off) = o;
    }
}

// ---------------- fp16 MMA GEMM: CTA 128x128, 4 warps, warp tile 64x64, BK=64 ----------------
static constexpr int BM = 128, BN = 128, TH = 128;
static constexpr int STAGES = 3;
static constexpr uint32_t TILE_BYTES = 16384;                 // 128x64 fp16
static constexpr uint32_t STAGE_BYTES = 2 * TILE_BYTES;       // A + B
static constexpr uint32_t EXTRA_OFF = STAGES * STAGE_BYTES;   // 98304
static constexpr uint32_t SMEM_BYTES = EXTRA_OFF + 1024;

__device__ __forceinline__ uint32_t smem_u32(const void* p) {
    uint32_t a;
    asm("{ .reg .u64 t; cvta.to.shared.u64 t, %1; cvt.u32.u64 %0, t; }"
        : "=r"(a) : "l"(p));
    return a;
}
__device__ __forceinline__ void cpasync16(uint32_t dst, const void* src) {
    size_t g = __cvta_generic_to_global(src);
    asm volatile("cp.async.cg.shared.global [%0], [%1], 16;" :: "r"(dst), "l"(g));
}
__device__ __forceinline__ void mma_f16(float* c, const uint32_t* a, const uint32_t* b) {
    asm volatile(
        "mma.sync.aligned.m16n8k16.row.col.f32.f16.f16.f32 "
        "{%0,%1,%2,%3}, {%4,%5,%6,%7}, {%8,%9}, {%0,%1,%2,%3};"
        : "+f"(c[0]), "+f"(c[1]), "+f"(c[2]), "+f"(c[3])
        : "r"(a[0]), "r"(a[1]), "r"(a[2]), "r"(a[3]), "r"(b[0]), "r"(b[1]));
}

// MODE 0: grid (128,2,1): Ph = headH @ UTH^T   (writes fp16 vector layout)
// MODE 1: grid (16,16,8): out = Ph @ depH^T + hs + ds + bias
template <int MODE>
__global__ void __launch_bounds__(TH, 2)
gemm_kernel(float* __restrict__ out, const float* __restrict__ eb) {
    extern __shared__ float sm[];
    const uint32_t sb = smem_u32(sm);

    const int tid = threadIdx.x;
    const int w = tid >> 5, lane = tid & 31;
    const int wm = w >> 1;          // 0..1 (M warp: 64 rows)
    const int wn = w & 1;           // 0..1 (N warp: 64 cols)
    const int x = blockIdx.x, y = blockIdx.y, z = blockIdx.z;

    const __half *Atile, *Btile;
    if (MODE == 0) {
        Atile = g_headH + (size_t)x * 4 * TILE_H;
        Btile = g_UTH   + (size_t)y * 4 * TILE_H;
    } else {
        Atile = g_Ph   + (size_t)(z * 16 + x) * 4 * TILE_H;
        Btile = g_depH + (size_t)(z * 16 + y) * 4 * TILE_H;
    }

    if (MODE == 1) {
        float* sex = sm + EXTRA_OFF / 4;
        sex[tid]       = g_hs[(size_t)z * Sn + (size_t)x * BM + tid];
        sex[128 + tid] = g_ds[(size_t)z * Sn + (size_t)y * BN + tid];
    }

    auto load_chunk = [&](int kt) {
        int stg = kt % STAGES;
        uint32_t baseA = sb + (uint32_t)stg * STAGE_BYTES;
        uint32_t baseB = baseA + TILE_BYTES;
        const __half* gA = Atile + (size_t)kt * TILE_H;
        const __half* gB = Btile + (size_t)kt * TILE_H;
        #pragma unroll
        for (int i = 0; i < 8; i++) {
            int cid = i * 128 + tid;
            cpasync16(baseA + (uint32_t)cid * 16, gA + cid * 8);
        }
        #pragma unroll
        for (int i = 0; i < 8; i++) {
            int cid = i * 128 + tid;
            cpasync16(baseB + (uint32_t)cid * 16, gB + cid * 8);
        }
        asm volatile("cp.async.commit_group;" ::: "memory");
    };

    float acc[4][8][4];
    #pragma unroll
    for (int i = 0; i < 4; i++)
        #pragma unroll
        for (int j = 0; j < 8; j++)
            #pragma unroll
            for (int t = 0; t < 4; t++) acc[i][j][t] = 0.f;

    load_chunk(0);
    load_chunk(1);

    const int rq = lane >> 2;       // 0..7
    const int kq = lane & 3;        // 0..3
    const uint32_t qoff = (uint32_t)rq * 256;
    const uint32_t xr = ((uint32_t)rq & 1) << 2;

    #pragma unroll 1
    for (int kt = 0; kt < 4; kt++) {
        if (kt == 3) { asm volatile("cp.async.wait_group 0;" ::: "memory"); }
        else         { asm volatile("cp.async.wait_group 1;" ::: "memory"); }
        __syncthreads();
        if (kt + 2 < 4) load_chunk(kt + 2);

        int stg = kt % STAGES;
        uint32_t baseA = sb + (uint32_t)stg * STAGE_BYTES;
        uint32_t baseB = baseA + TILE_BYTES;

        #pragma unroll
        for (int ks = 0; ks < 4; ks++) {
            uint32_t slotOff = ((((uint32_t)(ks * 4 + kq)) ^ xr) << 4);

            uint32_t a[4][4];
            #pragma unroll
            for (int i = 0; i < 4; i++) {
                uint32_t m = (uint32_t)(wm * 4 + i);
                uint32_t ad = baseA + m * 2048 + qoff + slotOff;
                uint4 v;
                asm volatile("ld.shared.v4.b32 {%0,%1,%2,%3}, [%4];"
                             : "=r"(v.x), "=r"(v.y), "=r"(v.z), "=r"(v.w) : "r"(ad));
                a[i][0] = v.x; a[i][1] = v.y; a[i][2] = v.z; a[i][3] = v.w;
            }

            uint32_t b[8][2];
            #pragma unroll
            for (int jp = 0; jp < 4; jp++) {
                uint32_t m = (uint32_t)(wn * 4 + jp);
                uint32_t bd = baseB + m * 2048 + qoff + slotOff;
                uint4 v;
                asm volatile("ld.shared.v4.b32 {%0,%1,%2,%3}, [%4];"
                             : "=r"(v.x), "=r"(v.y), "=r"(v.z), "=r"(v.w) : "r"(bd));
                b[2 * jp][0]     = v.x;   // (n,   k01)
                b[2 * jp][1]     = v.z;   // (n,   k89)
                b[2 * jp + 1][0] = v.y;   // (n+8, k01)
                b[2 * jp + 1][1] = v.w;   // (n+8, k89)
            }

            #pragma unroll
            for (int i = 0; i < 4; i++)
                #pragma unroll
                for (int j = 0; j < 8; j++)
                    mma_f16(acc[i][j], a[i], b[j]);
        }
    }

    if (MODE == 0) {
        // write Ph in the same fp16 vector layout
        int kc = y * 2 + wn;
        #pragma unroll
        for (int i = 0; i < 4; i++) {
            int m = wm * 4 + i;
            #pragma unroll
            for (int jp = 0; jp < 4; jp++) {
                int slotpos = (jp * 4 + kq) ^ (int)xr;
                uint4 o;
                o.x = pack2(acc[i][2 * jp][0],     acc[i][2 * jp][1]);
                o.y = pack2(acc[i][2 * jp][2],     acc[i][2 * jp][3]);
                o.z = pack2(acc[i][2 * jp + 1][0], acc[i][2 * jp + 1][1]);
                o.w = pack2(acc[i][2 * jp + 1][2], acc[i][2 * jp + 1][3]);
                size_t off = ((size_t)(x * 4 + kc)) * TILE_H
                           + ((m * 8 + rq) * 16 + slotpos) * 8;
                *(uint4*)(g_Ph + off) = o;
            }
        }
    } else {
        float bias = __ldg(eb);
        const float* shs = sm + EXTRA_OFF / 4;
        const float* sds = shs + 128;
        size_t aRow0 = (size_t)z * Sn + (size_t)x * BM;
        #pragma unroll
        for (int i = 0; i < 4; i++) {
            int rl = wm * 64 + i * 16 + rq;
            float hs0 = shs[rl] + bias;
            float hs1 = shs[rl + 8] + bias;
            size_t gr0 = (aRow0 + rl) * (size_t)Sn + (size_t)y * BN;
            #pragma unroll
            for (int j = 0; j < 8; j++) {
                int c = wn * 64 + j * 8 + kq * 2;
                float d0 = sds[c], d1 = sds[c + 1];
                *(float2*)(out + gr0 + c) =
                    make_float2(acc[i][j][0] + hs0 + d0, acc[i][j][1] + hs0 + d1);
                *(float2*)(out + gr0 + 8 * (size_t)Sn + c) =
                    make_float2(acc[i][j][2] + hs1 + d0, acc[i][j][3] + hs1 + d1);
            }
        }
    }
}

// ---------------- kernel_launch ----------------
extern "C" void kernel_launch(void* const* d_in, const int* in_sizes, int n_in,
                              void* d_out, int out_size) {
    const float* head = (const float*)d_in[0];
    const float* dep  = (const float*)d_in[1];
    const float* U    = (const float*)d_in[2];
    const float* W    = (const float*)d_in[3];
    const float* eb   = (const float*)d_in[4];
    float* out = (float*)d_out;
    (void)in_sizes; (void)n_in; (void)out_size;

    cudaFuncSetAttribute(gemm_kernel<0>,
                         cudaFuncAttributeMaxDynamicSharedMemorySize, SMEM_BYTES);
    cudaFuncSetAttribute(gemm_kernel<1>,
                         cudaFuncAttributeMaxDynamicSharedMemorySize, SMEM_BYTES);

    // 1) prep: hs/ds dots + fp16 vector-layout headH/depH/UTH (LDG.128 staging)
    prep_all<<<HEAD_BLOCKS + DEP_BLOCKS + UT_BLOCKS, 256>>>(head, dep, W, U);
    // 2) stage-1: Ph = headH @ UTH^T
    gemm_kernel<0><<<dim3(MROWS / BM, 2, 1), TH, SMEM_BYTES>>>(out, eb);
    // 3) stage-2: out[b] = Ph[b] @ depH[b]^T + hs + ds + bias
    gemm_kernel<1><<<dim3(Sn / BM, Sn / BN, Bn), TH, SMEM_BYTES>>>(out, eb);
}